// round 14
// baseline (speedup 1.0000x reference)
#include <cuda_runtime.h>
#include <math.h>

// Problem constants (fixed by setup_inputs)
#define M 16384
#define P 512
#define K 10
#define NMAT 11          // 10 class matrices + 1 global
#define EPSV 0.01f
#define CB 8             // cluster CTAs per matrix

// ---------------- device scratch (no allocs allowed) ----------------
__device__ __align__(16) float g_A[NMAT * P * P];   // raw grams -> B -> L (lower triangle only)
__device__ int g_idx[M];
__device__ int g_cnt[16];
__device__ int g_off[16];
__device__ int g_cur[16];
__device__ int g_done;
__device__ float g_sums[NMAT];

// ---------------- cluster barrier ----------------
__device__ __forceinline__ void cluster_sync() {
    asm volatile("barrier.cluster.arrive.aligned;" ::: "memory");
    asm volatile("barrier.cluster.wait.aligned;" ::: "memory");
}

// ---------------- f32x2 packed FMA helpers (sm_103a) ----------------
__device__ __forceinline__ unsigned long long pack2(float x, float y) {
    unsigned long long r;
    asm("mov.b64 %0, {%1,%2};" : "=l"(r) : "f"(x), "f"(y));
    return r;
}
__device__ __forceinline__ void unpack2(unsigned long long v, float &a, float &b) {
    asm("mov.b64 {%0,%1}, %2;" : "=f"(a), "=f"(b) : "l"(v));
}
__device__ __forceinline__ void ffma2(unsigned long long &d, unsigned long long a, unsigned long long b) {
    asm("fma.rn.f32x2 %0, %1, %2, %0;" : "+l"(d) : "l"(a), "l"(b));
}

// ---------------- zero scratch + flags (every launch: replay-deterministic) ----------------
__global__ void zeroA_kernel() {
    int n = K * P * P;   // class grams are atomic targets; matrix 10 lower fully written by assemble
    for (int i = blockIdx.x * blockDim.x + threadIdx.x; i < n; i += gridDim.x * blockDim.x)
        g_A[i] = 0.f;
    if (blockIdx.x == 0 && threadIdx.x < 17) {
        if (threadIdx.x < 16) g_cnt[threadIdx.x] = 0;
        else g_done = 0;
    }
}

// ---------------- class histogram (multi-block) ----------------
__global__ void hist_kernel(const int* __restrict__ Y) {
    __shared__ int h[K];
    int tid = threadIdx.x;
    if (tid < K) h[tid] = 0;
    __syncthreads();
    for (int i = blockIdx.x * blockDim.x + tid; i < M; i += gridDim.x * blockDim.x) {
        int c = Y[i];
        if (c >= 0 && c < K) atomicAdd(&h[c], 1);
    }
    __syncthreads();
    if (tid < K) atomicAdd(&g_cnt[tid], h[tid]);
}

__global__ void prefix_kernel() {
    if (threadIdx.x == 0) {
        int acc = 0;
        for (int c = 0; c < K; c++) {
            g_off[c] = acc;
            g_cur[c] = acc;
            acc += g_cnt[c];
        }
    }
}

// ---------------- scatter row indices by class ----------------
__global__ void scatter_kernel(const int* __restrict__ Y) {
    for (int i = blockIdx.x * blockDim.x + threadIdx.x; i < M; i += gridDim.x * blockDim.x) {
        int c = Y[i];
        if (c < 0 || c >= K) continue;
        int pos = atomicAdd(&g_cur[c], 1);
        g_idx[pos] = i;
    }
}

// ---------------- per-class SYRK: lower 128x128 tiles, f32x2 FMAs ----------------
#define CH 16
#define NSPLIT 8

__global__ __launch_bounds__(256, 2) void gram_kernel(const float* __restrict__ X) {
    __shared__ __align__(16) float As[CH][128];
    __shared__ __align__(16) float Bs[CH][128];
    __shared__ int rid[CH];

    const int TI[10] = {0, 1, 1, 2, 2, 2, 3, 3, 3, 3};
    const int TJ[10] = {0, 0, 1, 0, 1, 2, 0, 1, 2, 3};

    int c  = blockIdx.y;
    int ti = TI[blockIdx.x];
    int tj = TJ[blockIdx.x];
    int off = g_off[c], cnt = g_cnt[c];
    int s = blockIdx.z;
    int rbeg = off + (cnt * s) / NSPLIT;
    int rend = off + (cnt * (s + 1)) / NSPLIT;

    int tid = threadIdx.x;
    int tx = tid & 15, ty = tid >> 4;

    unsigned long long acc[8][4];
#pragma unroll
    for (int r = 0; r < 8; r++)
#pragma unroll
        for (int q = 0; q < 4; q++) acc[r][q] = 0ull;

    for (int r0 = rbeg; r0 < rend; r0 += CH) {
        __syncthreads();
        if (tid < CH) rid[tid] = (r0 + tid < rend) ? g_idx[r0 + tid] : -1;
        __syncthreads();
        for (int e = tid; e < CH * 32; e += 256) {
            int rr = e >> 5, f = e & 31;
            int gi = rid[rr];
            float4 va = make_float4(0.f, 0.f, 0.f, 0.f);
            float4 vb = va;
            if (gi >= 0) {
                const float* rp = X + (long long)gi * P;
                va = *(const float4*)(rp + ti * 128 + f * 4);
                vb = *(const float4*)(rp + tj * 128 + f * 4);
            }
            *(float4*)&As[rr][f * 4] = va;
            *(float4*)&Bs[rr][f * 4] = vb;
        }
        __syncthreads();
        // software-pipelined: prefetch kk+1 operands before kk's FMAs
        float4 a0 = *(const float4*)&As[0][ty * 8];
        float4 a1 = *(const float4*)&As[0][ty * 8 + 4];
        ulonglong2 bb0 = *(const ulonglong2*)&Bs[0][tx * 8];
        ulonglong2 bb1 = *(const ulonglong2*)&Bs[0][tx * 8 + 4];
#pragma unroll
        for (int kk = 0; kk < CH; kk++) {
            float4 na0 = a0, na1 = a1;
            ulonglong2 nb0 = bb0, nb1 = bb1;
            if (kk + 1 < CH) {
                na0 = *(const float4*)&As[kk + 1][ty * 8];
                na1 = *(const float4*)&As[kk + 1][ty * 8 + 4];
                nb0 = *(const ulonglong2*)&Bs[kk + 1][tx * 8];
                nb1 = *(const ulonglong2*)&Bs[kk + 1][tx * 8 + 4];
            }
            unsigned long long bv[4] = {bb0.x, bb0.y, bb1.x, bb1.y};
            float av[8] = {a0.x, a0.y, a0.z, a0.w, a1.x, a1.y, a1.z, a1.w};
#pragma unroll
            for (int r = 0; r < 8; r++) {
                unsigned long long ar = pack2(av[r], av[r]);
#pragma unroll
                for (int q = 0; q < 4; q++) ffma2(acc[r][q], ar, bv[q]);
            }
            a0 = na0; a1 = na1; bb0 = nb0; bb1 = nb1;
        }
    }

    float* Ac = g_A + c * P * P;
    bool dg = (ti == tj);
#pragma unroll
    for (int r = 0; r < 8; r++) {
        int i = ti * 128 + ty * 8 + r;
#pragma unroll
        for (int q = 0; q < 4; q++) {
            float v0, v1;
            unpack2(acc[r][q], v0, v1);
            int j = tj * 128 + tx * 8 + q * 2;
            if (!dg || j <= i)     atomicAdd(&Ac[i * P + j], v0);
            if (!dg || j + 1 <= i) atomicAdd(&Ac[i * P + j + 1], v1);
        }
    }
}

// ---------------- B = I + scal*Gram (lower), B[10] = I + 3.125*sum ----------------
__global__ void assemble_kernel() {
    int e = blockIdx.x * blockDim.x + threadIdx.x;
    if (e >= P * P) return;
    int i = e >> 9, j = e & (P - 1);
    if (j > i) return;
    float add = (i == j) ? 1.f : 0.f;
    float s = 0.f;
#pragma unroll
    for (int c = 0; c < K; c++) {
        float v = g_A[c * P * P + e];
        s += v;
        float trPi = (float)g_cnt[c] + 1e-8f;
        float scal = (float)P / (trPi * EPSV);
        g_A[c * P * P + e] = scal * v + add;
    }
    float scal_g = (float)P / ((float)M * EPSV);   // 3.125
    g_A[K * P * P + e] = scal_g * s + add;
}

// ---------------- in-smem 64x64 factor + write L to global (256 threads) ----------------
__device__ __forceinline__ void factor_write(float* sA, float* sInv, float* A, int kb) {
    int tid = threadIdx.x;
    for (int j = 0; j < 64; j++) {
        __syncthreads();
        float invd = 1.0f / sA[j * 65 + j];
        for (int i = j + 1 + (tid >> 4); i < 64; i += 16) {
            float cij = sA[i * 65 + j] * invd;
            for (int t = j + 1 + (tid & 15); t <= i; t += 16)
                sA[i * 65 + t] -= cij * sA[t * 65 + j];
        }
    }
    __syncthreads();
    if (tid < 64) sInv[tid] = rsqrtf(sA[tid * 65 + tid]);
    __syncthreads();
    for (int e = tid; e < 4096; e += 256) {
        int i = e >> 6, j = e & 63;
        if (j <= i) A[(kb + i) * P + kb + j] = sA[i * 65 + j] * sInv[j];
    }
}

// ---------------- fused Cholesky: one 8-CTA cluster per matrix ----------------
// Per step: all CTAs TRSM (rows interleaved) | sync | CTA0 updates+factors the
// NEXT diag tile in smem while CTAs 1..7 update remaining trailing tiles | sync.
// No min-blocks clause: w[64] stays in registers (the R12 spill bug).
__global__ __launch_bounds__(256) __cluster_dims__(CB, 1, 1)
void chol_kernel(float* __restrict__ out) {
    __shared__ float sA[64 * 65];
    __shared__ float sB[64 * 65];
    __shared__ float sInv[64];
    __shared__ float red[256];

    int c = blockIdx.y;
    int b = blockIdx.x;          // cluster rank
    int tid = threadIdx.x;
    float* A = g_A + c * P * P;

    // ---- pre-step: CTA0 factors tile (0,0) ----
    if (b == 0) {
        for (int e = tid; e < 4096; e += 256) {
            int i = e >> 6, j = e & 63;
            sA[i * 65 + j] = (j <= i) ? A[i * P + j] : 0.f;
        }
        factor_write(sA, sInv, A, 0);
    }
    cluster_sync();

    for (int k = 0; k < 7; k++) {
        int kb = k * 64;
        int rows = P - kb - 64;

        // ---- TRSM: rows interleaved across cluster, w[] in registers ----
        for (int e = tid; e < 4096; e += 256) {
            int i = e >> 6, j = e & 63;
            sA[i * 65 + j] = (j <= i) ? A[(kb + i) * P + kb + j] : 0.f;
        }
        __syncthreads();
        if (tid < 64) sInv[tid] = 1.0f / sA[tid * 65 + tid];
        __syncthreads();
        int rl = b + CB * tid;
        if (rl < rows) {
            int row = kb + 64 + rl;
            float w[64];
            const float* rp = A + row * P + kb;
#pragma unroll
            for (int q = 0; q < 16; q++) {
                float4 v = *(const float4*)(rp + q * 4);
                w[4 * q] = v.x; w[4 * q + 1] = v.y; w[4 * q + 2] = v.z; w[4 * q + 3] = v.w;
            }
#pragma unroll
            for (int j = 0; j < 64; j++) {
                float xj = w[j] * sInv[j];
                w[j] = xj;
#pragma unroll
                for (int t = j + 1; t < 64; t++) w[t] -= xj * sA[t * 65 + j];
            }
            float* wp = A + row * P + kb;
#pragma unroll
            for (int q = 0; q < 16; q++)
                *(float4*)(wp + q * 4) = make_float4(w[4 * q], w[4 * q + 1], w[4 * q + 2], w[4 * q + 3]);
        }
        cluster_sync();

        // ---- update phase: CTA0 fuses next-diag update + factor; others SYRK ----
        int nt = 7 - k;
        int tiles = nt * (nt + 1) / 2;
        int tx = tid & 15, ty = tid >> 4;

        if (b == 0) {
            int I0 = kb + 64;
            // panel transposed: sB[t][i] = A[I0+i][kb+t]
            for (int e = tid; e < 4096; e += 256) {
                int i = e >> 6, t = e & 63;
                sB[t * 65 + i] = A[(I0 + i) * P + kb + t];
            }
            __syncthreads();
            float acc[4][4];
#pragma unroll
            for (int r = 0; r < 4; r++)
#pragma unroll
                for (int s = 0; s < 4; s++)
                    acc[r][s] = A[(I0 + ty * 4 + r) * P + I0 + tx * 4 + s];
#pragma unroll 4
            for (int t = 0; t < 64; t++) {
                float a[4], bv[4];
#pragma unroll
                for (int r = 0; r < 4; r++) a[r] = sB[t * 65 + ty * 4 + r];
#pragma unroll
                for (int s = 0; s < 4; s++) bv[s] = sB[t * 65 + tx * 4 + s];
#pragma unroll
                for (int r = 0; r < 4; r++)
#pragma unroll
                    for (int s = 0; s < 4; s++) acc[r][s] -= a[r] * bv[s];
            }
#pragma unroll
            for (int r = 0; r < 4; r++)
#pragma unroll
                for (int s = 0; s < 4; s++)
                    sA[(ty * 4 + r) * 65 + tx * 4 + s] = acc[r][s];   // upper garbage unused
            __syncthreads();
            factor_write(sA, sInv, A, I0);
        } else {
            for (int l = b; l < tiles; l += CB - 1) {   // l>=1: diag tile owned by CTA0
                int bi = 0, ll = l;
                while (ll >= bi + 1) { ll -= bi + 1; bi++; }
                int bj = ll;
                int I = kb + 64 + bi * 64;
                int J = kb + 64 + bj * 64;

                __syncthreads();
                for (int e = tid; e < 4096; e += 256) {
                    int r = e >> 6, t = e & 63;
                    sA[t * 65 + r] = A[(I + r) * P + kb + t];
                    sB[t * 65 + r] = A[(J + r) * P + kb + t];
                }
                __syncthreads();

                float acc[4][4];
#pragma unroll
                for (int r = 0; r < 4; r++)
#pragma unroll
                    for (int s = 0; s < 4; s++) acc[r][s] = 0.f;
#pragma unroll 4
                for (int t = 0; t < 64; t++) {
                    float a[4], bv[4];
#pragma unroll
                    for (int r = 0; r < 4; r++) a[r] = sA[t * 65 + ty * 4 + r];
#pragma unroll
                    for (int s = 0; s < 4; s++) bv[s] = sB[t * 65 + tx * 4 + s];
#pragma unroll
                    for (int r = 0; r < 4; r++)
#pragma unroll
                        for (int s = 0; s < 4; s++) acc[r][s] += a[r] * bv[s];
                }
                bool dg = (bi == bj);
#pragma unroll
                for (int r = 0; r < 4; r++) {
                    int li = ty * 4 + r;
#pragma unroll
                    for (int s = 0; s < 4; s++) {
                        int lj = tx * 4 + s;
                        if (!dg || lj <= li)
                            A[(I + li) * P + J + lj] -= acc[r][s];
                    }
                }
            }
        }
        cluster_sync();
    }

    // ---- final: CTA0 reduces log diag (all diag tiles written by CTA0 itself) ----
    if (b == 0) {
        float s = 0.f;
        for (int i = tid; i < P; i += 256) s += logf(A[i * P + i]);
        red[tid] = s;
        __syncthreads();
        for (int st = 128; st > 0; st >>= 1) {
            if (tid < st) red[tid] += red[tid + st];
            __syncthreads();
        }
        if (tid == 0) {
            g_sums[c] = red[0];
            __threadfence();
            int old = atomicAdd(&g_done, 1);
            if (old == NMAT - 1) {
                __threadfence();
                float comp = 0.f;
                for (int cc = 0; cc < K; cc++) {
                    float trPi = (float)g_cnt[cc] + 1e-8f;
                    comp += g_sums[cc] * trPi / (float)M;
                }
                out[0] = g_sums[K];   // discrimn = sum(log diag L) = logdet/2
                out[1] = comp;
            }
        }
    }
}

// ---------------- launch ----------------
extern "C" void kernel_launch(void* const* d_in, const int* in_sizes, int n_in,
                              void* d_out, int out_size) {
    const float* X = (const float*)d_in[0];
    const int* Y = (const int*)d_in[1];   // int32: JAX demotes int64 without x64 mode
    float* out = (float*)d_out;

    zeroA_kernel<<<2048, 256>>>();
    hist_kernel<<<64, 256>>>(Y);
    prefix_kernel<<<1, 32>>>();
    scatter_kernel<<<64, 256>>>(Y);
    gram_kernel<<<dim3(10, K, NSPLIT), 256>>>(X);
    assemble_kernel<<<(P * P + 255) / 256, 256>>>();
    chol_kernel<<<dim3(CB, NMAT), 256>>>(out);   // cluster (8,1,1) per matrix
}